// round 4
// baseline (speedup 1.0000x reference)
#include <cuda_runtime.h>
#include <cuda_fp16.h>
#include <cstdint>

// ============================================================================
// Problem constants
// ============================================================================
#define B_DIM 8
#define T_DIM 65536
#define TPB_TILES 4          // 128-t sub-tiles per block
#define TILE_T 128
#define XROWS 162            // staged rows: t0-17 .. t0+144
#define XPITCH 144           // bytes per x row (64 halves + pad) -> conflict-free LDSM
#define WPITCH 144           // bytes per w row (o-major, 64 c halves + pad)
#define WJ_BYTES (64 * WPITCH)        // 9216 per tap
#define W_BYTES (9 * WJ_BYTES)        // 82944
#define XBUF_BYTES (XROWS * XPITCH)   // 23328

// smem layout (bytes)
#define OFF_BIAS 0
#define OFF_W    256
#define OFF_X0   (OFF_W + W_BYTES)            // 83200
#define OFF_X1   (OFF_X0 + XBUF_BYTES)        // 106528
#define SMEM_TOTAL (OFF_X1 + XBUF_BYTES)      // 129856

// ============================================================================
// Scratch (device globals — no allocation allowed)
// ============================================================================
__device__ __half g_xh[(size_t)B_DIM * T_DIM * 64];  // x as [b][t][c] fp16
__device__ __half g_wh[9 * 64 * 64];                 // w as [j][o][c] fp16

// ============================================================================
// Helpers
// ============================================================================
__device__ __forceinline__ uint32_t smem_to_u32(const void* p) {
    uint32_t a;
    asm("{ .reg .u64 t; cvta.to.shared.u64 t, %1; cvt.u32.u64 %0, t; }" : "=r"(a) : "l"(p));
    return a;
}

__device__ __forceinline__ void cp_async16(uint32_t dst, const void* src, int src_bytes) {
    asm volatile("cp.async.cg.shared.global [%0], [%1], 16, %2;"
                 :: "r"(dst), "l"(src), "r"(src_bytes) : "memory");
}
#define CP_COMMIT() asm volatile("cp.async.commit_group;" ::: "memory")
#define CP_WAIT0()  asm volatile("cp.async.wait_group 0;" ::: "memory")

__device__ __forceinline__ void ldsm4(uint32_t& r0, uint32_t& r1, uint32_t& r2, uint32_t& r3,
                                      uint32_t addr) {
    asm volatile("ldmatrix.sync.aligned.m8n8.x4.shared.b16 {%0,%1,%2,%3}, [%4];"
                 : "=r"(r0), "=r"(r1), "=r"(r2), "=r"(r3) : "r"(addr));
}

__device__ __forceinline__ void mma16816(float* c, const uint32_t* a, const uint32_t* b) {
    asm volatile("mma.sync.aligned.m16n8k16.row.col.f32.f16.f16.f32 "
                 "{%0,%1,%2,%3}, {%4,%5,%6,%7}, {%8,%9}, {%0,%1,%2,%3};"
                 : "+f"(c[0]), "+f"(c[1]), "+f"(c[2]), "+f"(c[3])
                 : "r"(a[0]), "r"(a[1]), "r"(a[2]), "r"(a[3]), "r"(b[0]), "r"(b[1]));
}

// ============================================================================
// Prologue 1: weights fp32 [o][c][9] -> fp16 [j][o][c]
// ============================================================================
__global__ void ta_conv_weights(const float* __restrict__ w) {
    int i = blockIdx.x * 256 + threadIdx.x;
    if (i >= 9 * 64 * 64) return;
    int j = i >> 12;
    int rem = i & 4095;
    int o = rem >> 6;
    int c = rem & 63;
    g_wh[j * 4096 + o * 64 + c] = __float2half_rn(w[(o * 64 + c) * 9 + j]);
}

// ============================================================================
// Prologue 2: x fp32 [b][c][t] -> fp16 [b][t][c]
// ============================================================================
__global__ __launch_bounds__(256) void ta_transpose_x(const float* __restrict__ x) {
    __shared__ float s[64][65];
    int b = blockIdx.y;
    int t0 = blockIdx.x * 64;
    int tid = threadIdx.x;
    for (int i = tid; i < 64 * 64; i += 256) {
        int c = i >> 6, tl = i & 63;
        s[c][tl] = x[((size_t)(b * 64 + c)) * T_DIM + t0 + tl];
    }
    __syncthreads();
    for (int i = tid; i < 64 * 32; i += 256) {
        int row = i >> 5, cp = i & 31;
        __half2 h = __floats2half2_rn(s[2 * cp][row], s[2 * cp + 1][row]);
        *((__half2*)(g_xh + ((size_t)b * T_DIM + t0 + row) * 64) + cp) = h;
    }
}

// ============================================================================
// Main kernel: block = 4 sub-tiles of [128 t][64 o], cp.async double-buffered.
//   8 warps: wm = wid&3 (t quadrant, 32 rows), wn = wid>>2 (o half, 32 cols).
// ============================================================================
__global__ __launch_bounds__(256) void ta_main(const float* __restrict__ bias,
                                               float* __restrict__ out) {
    extern __shared__ char smem[];
    uint32_t sb = smem_to_u32(smem);
    int tid = threadIdx.x;
    int wid = tid >> 5;
    int lane = tid & 31;

    int b = blockIdx.x >> 7;                    // 128 blocks per batch element
    int tile0 = (blockIdx.x & 127) * TPB_TILES;

    if (tid < 64) ((float*)(smem + OFF_BIAS))[tid] = bias[tid];

    // ---- issue weights + first x tile via cp.async (one group) ----
    {
        const char* wsrc = (const char*)g_wh;
        for (int i = tid; i < 9 * 64 * 8; i += 256) {
            int row = i >> 3, ch = i & 7;
            cp_async16(sb + OFF_W + row * WPITCH + ch * 16, wsrc + row * 128 + ch * 16, 16);
        }
        int t0 = tile0 * TILE_T;
        for (int i = tid; i < XROWS * 8; i += 256) {
            int s = i >> 3, ch = i & 7;
            int t = t0 - 17 + s;
            const char* src = (const char*)(g_xh + ((size_t)b * T_DIM + t) * 64) + ch * 16;
            cp_async16(sb + OFF_X0 + s * XPITCH + ch * 16, src,
                       ((unsigned)t < (unsigned)T_DIM) ? 16 : 0);
        }
        CP_COMMIT();
    }

    const int wm = wid & 3;
    const int wn = wid >> 2;

    // lane-dependent ldmatrix address components
    const int a_lrow = lane & 15;
    const int a_lcol = (lane >> 4) << 3;                 // 0 or 8 (halves)
    const int b_lrow = ((lane & 16) >> 1) + (lane & 7);  // 0..15
    const int b_lcol = lane & 8;                         // 0 or 8 (halves)

    const uint32_t wbase = sb + OFF_W;
    const uint32_t xoff[2] = {sb + OFF_X0, sb + OFF_X1};

    for (int it = 0; it < TPB_TILES; it++) {
        int t0 = (tile0 + it) * TILE_T;

        CP_WAIT0();
        __syncthreads();   // tile 'it' (buffer it&1) + weights now visible to all

        // ---- prefetch tile it+1 into the other buffer ----
        if (it + 1 < TPB_TILES) {
            int tn0 = t0 + TILE_T;
            uint32_t dstb = xoff[(it + 1) & 1];
            for (int i = tid; i < XROWS * 8; i += 256) {
                int s = i >> 3, ch = i & 7;
                int t = tn0 - 17 + s;
                const char* src = (const char*)(g_xh + ((size_t)b * T_DIM + t) * 64) + ch * 16;
                cp_async16(dstb + s * XPITCH + ch * 16, src,
                           ((unsigned)t < (unsigned)T_DIM) ? 16 : 0);
            }
            CP_COMMIT();
        }

        const uint32_t xbase = xoff[it & 1];

        float acc[2][4][4];
        #pragma unroll
        for (int mi = 0; mi < 2; mi++)
            #pragma unroll
            for (int ni = 0; ni < 4; ni++)
                #pragma unroll
                for (int r = 0; r < 4; r++) acc[mi][ni][r] = 0.0f;

        const int delta[9] = {-17, -16, -15, -1, 0, 1, 15, 16, 17};

        #pragma unroll
        for (int j = 0; j < 9; j++) {
            const int tb = 17 + wm * 32 + delta[j];      // smem row base for this tap
            const uint32_t wj = wbase + j * WJ_BYTES;
            #pragma unroll
            for (int kk = 0; kk < 4; kk++) {
                const int c0 = kk * 16;
                uint32_t a0[4], a1[4], b0[4], b1[4];
                ldsm4(a0[0], a0[1], a0[2], a0[3],
                      xbase + (uint32_t)(tb + a_lrow) * XPITCH + (uint32_t)(c0 + a_lcol) * 2);
                ldsm4(a1[0], a1[1], a1[2], a1[3],
                      xbase + (uint32_t)(tb + 16 + a_lrow) * XPITCH + (uint32_t)(c0 + a_lcol) * 2);
                ldsm4(b0[0], b0[1], b0[2], b0[3],
                      wj + (uint32_t)(wn * 32 + b_lrow) * WPITCH + (uint32_t)(c0 + b_lcol) * 2);
                ldsm4(b1[0], b1[1], b1[2], b1[3],
                      wj + (uint32_t)(wn * 32 + 16 + b_lrow) * WPITCH + (uint32_t)(c0 + b_lcol) * 2);

                mma16816(acc[0][0], a0, b0 + 0);
                mma16816(acc[0][1], a0, b0 + 2);
                mma16816(acc[0][2], a0, b1 + 0);
                mma16816(acc[0][3], a0, b1 + 2);
                mma16816(acc[1][0], a1, b0 + 0);
                mma16816(acc[1][1], a1, b0 + 2);
                mma16816(acc[1][2], a1, b1 + 0);
                mma16816(acc[1][3], a1, b1 + 2);
            }
        }

        // ---- epilogue: D fragment (row=t, col=o), add bias, store ----
        {
            const float* sbias = (const float*)(smem + OFF_BIAS);
            int trow = t0 + wm * 32 + (lane >> 2);
            int ocol = wn * 32 + 2 * (lane & 3);
            #pragma unroll
            for (int mi = 0; mi < 2; mi++) {
                #pragma unroll
                for (int ni = 0; ni < 4; ni++) {
                    int t = trow + mi * 16;
                    int o = ocol + ni * 8;
                    size_t base = ((size_t)b * 64 + o) * T_DIM + t;
                    float bz0 = sbias[o], bz1 = sbias[o + 1];
                    out[base] = acc[mi][ni][0] + bz0;
                    out[base + T_DIM] = acc[mi][ni][1] + bz1;
                    out[base + 8] = acc[mi][ni][2] + bz0;
                    out[base + T_DIM + 8] = acc[mi][ni][3] + bz1;
                }
            }
        }
        // no trailing sync needed: next iter starts with CP_WAIT0 + __syncthreads,
        // and the buffer being overwritten next is the one read at it-1.
    }
}

// ============================================================================
// Launch
// ============================================================================
extern "C" void kernel_launch(void* const* d_in, const int* in_sizes, int n_in,
                              void* d_out, int out_size) {
    const float* x = (const float*)d_in[0];
    const float* w = (const float*)d_in[1];
    const float* bias = (const float*)d_in[2];
    float* out = (float*)d_out;

    cudaFuncSetAttribute(ta_main, cudaFuncAttributeMaxDynamicSharedMemorySize, SMEM_TOTAL);

    ta_conv_weights<<<(9 * 64 * 64 + 255) / 256, 256>>>(w);
    ta_transpose_x<<<dim3(T_DIM / 64, B_DIM), 256>>>(x);
    ta_main<<<(B_DIM * T_DIM / TILE_T) / TPB_TILES, 256, SMEM_TOTAL>>>(bias, out);
}

// round 6
// speedup vs baseline: 1.3707x; 1.3707x over previous
#include <cuda_runtime.h>
#include <cuda_fp16.h>
#include <cstdint>

// ============================================================================
// Problem constants
// ============================================================================
#define B_DIM 8
#define T_DIM 65536
#define TILE_M 512            // t-rows per block (one pass, 8 warps x 64 rows)
#define XROWS 546             // staged rows: t0-17 .. t0+528
#define WJ_BYTES (64 * 128)   // 8192 per tap (o-major rows of 128B, swizzled)
#define W_BYTES (9 * WJ_BYTES)  // 73728

// smem layout (bytes)
#define OFF_BIAS 0
#define OFF_W    256
#define OFF_X    (OFF_W + W_BYTES)          // 73984 (128B aligned)
#define SMEM_TOTAL (OFF_X + XROWS * 128)    // 143872

// ============================================================================
// Scratch (device globals — no allocation allowed)
// ============================================================================
__device__ __half g_xh[(size_t)B_DIM * T_DIM * 64];  // x as [b][t][c] fp16
__device__ __half g_wh[9 * 64 * 64];                 // w as [j][o][c] fp16

// ============================================================================
// Helpers
// ============================================================================
__device__ __forceinline__ uint32_t smem_to_u32(const void* p) {
    uint32_t a;
    asm("{ .reg .u64 t; cvta.to.shared.u64 t, %1; cvt.u32.u64 %0, t; }" : "=r"(a) : "l"(p));
    return a;
}

__device__ __forceinline__ void cp_async16(uint32_t dst, const void* src, int src_bytes) {
    asm volatile("cp.async.cg.shared.global [%0], [%1], 16, %2;"
                 :: "r"(dst), "l"(src), "r"(src_bytes) : "memory");
}
#define CP_COMMIT() asm volatile("cp.async.commit_group;" ::: "memory")
#define CP_WAIT0()  asm volatile("cp.async.wait_group 0;" ::: "memory")

__device__ __forceinline__ void ldsm4(uint32_t& r0, uint32_t& r1, uint32_t& r2, uint32_t& r3,
                                      uint32_t addr) {
    asm volatile("ldmatrix.sync.aligned.m8n8.x4.shared.b16 {%0,%1,%2,%3}, [%4];"
                 : "=r"(r0), "=r"(r1), "=r"(r2), "=r"(r3) : "r"(addr));
}

__device__ __forceinline__ void mma16816(float* c, const uint32_t* a, const uint32_t* b) {
    asm volatile("mma.sync.aligned.m16n8k16.row.col.f32.f16.f16.f32 "
                 "{%0,%1,%2,%3}, {%4,%5,%6,%7}, {%8,%9}, {%0,%1,%2,%3};"
                 : "+f"(c[0]), "+f"(c[1]), "+f"(c[2]), "+f"(c[3])
                 : "r"(a[0]), "r"(a[1]), "r"(a[2]), "r"(a[3]), "r"(b[0]), "r"(b[1]));
}

// ============================================================================
// Prologue (single kernel): x fp32 [b][c][t] -> fp16 [b][t][c]  (blocks x<1024)
//                           w fp32 [o][c][9] -> fp16 [j][o][c]  (blocks x==1024)
// ============================================================================
__global__ __launch_bounds__(256) void ta_prep(const float* __restrict__ x,
                                               const float* __restrict__ w) {
    int tid = threadIdx.x;
    if (blockIdx.x == gridDim.x - 1) {
        // weights: 36864 elements split across 8 y-blocks
        int base = blockIdx.y * 4608;
        for (int k = tid; k < 4608; k += 256) {
            int i = base + k;
            int j = i >> 12;
            int rem = i & 4095;
            int o = rem >> 6;
            int c = rem & 63;
            g_wh[j * 4096 + o * 64 + c] = __float2half_rn(w[(o * 64 + c) * 9 + j]);
        }
        return;
    }
    __shared__ float s[64][65];
    int b = blockIdx.y;
    int t0 = blockIdx.x * 64;
    for (int i = tid; i < 64 * 64; i += 256) {
        int c = i >> 6, tl = i & 63;
        s[c][tl] = x[((size_t)(b * 64 + c)) * T_DIM + t0 + tl];
    }
    __syncthreads();
    for (int i = tid; i < 64 * 32; i += 256) {
        int row = i >> 5, cp = i & 31;
        __half2 h = __floats2half2_rn(s[2 * cp][row], s[2 * cp + 1][row]);
        *((__half2*)(g_xh + ((size_t)b * T_DIM + t0 + row) * 64) + cp) = h;
    }
}

// ============================================================================
// Main kernel: block = [512 t][64 o]; 8 warps, each a 64x64 warp tile (Wn=1).
//   Smem: swizzled (SW128 XOR) x tile (546 rows) + weights (576 rows).
//   Per warp: acc 64x64 fp32, K = 9 taps x 4 k16-steps, mma.sync fp16.
// ============================================================================
__global__ __launch_bounds__(256) void ta_main(const float* __restrict__ bias,
                                               float* __restrict__ out) {
    extern __shared__ char smem[];
    uint32_t sb = smem_to_u32(smem);
    int tid = threadIdx.x;
    int wid = tid >> 5;
    int lane = tid & 31;

    int b = blockIdx.x >> 7;                    // 128 blocks per batch element
    int t0 = (blockIdx.x & 127) * TILE_M;

    if (tid < 64) ((float*)(smem + OFF_BIAS))[tid] = bias[tid];

    // ---- stage weights + x tile via cp.async, SW128-XOR swizzled ----
    {
        const char* wsrc = (const char*)g_wh;
        for (int i = tid; i < 576 * 8; i += 256) {
            int row = i >> 3, ch = i & 7;
            uint32_t dst = sb + OFF_W + row * 128 + ((ch ^ (row & 7)) * 16);
            cp_async16(dst, wsrc + row * 128 + ch * 16, 16);
        }
        for (int i = tid; i < XROWS * 8; i += 256) {
            int s = i >> 3, ch = i & 7;
            int t = t0 - 17 + s;
            const char* src = (const char*)(g_xh + ((size_t)b * T_DIM + t) * 64) + ch * 16;
            uint32_t dst = sb + OFF_X + s * 128 + ((ch ^ (s & 7)) * 16);
            cp_async16(dst, src, ((unsigned)t < (unsigned)T_DIM) ? 16 : 0);
        }
        CP_COMMIT();
    }

    // lane-dependent ldmatrix address components
    const int a_lrow = lane & 15;
    const int a_lcol = (lane >> 4) << 3;                 // 0 or 8 (halves)
    const int b_lrow = ((lane & 16) >> 1) + (lane & 7);  // 0..15
    const int b_lcol = lane & 8;                         // 0 or 8 (halves)
    const int b_sw = b_lrow & 7;                         // B swizzle phase (const per lane)

    const uint32_t wbase = sb + OFF_W;
    const uint32_t xbase = sb + OFF_X;

    float acc[4][8][4];
    #pragma unroll
    for (int mi = 0; mi < 4; mi++)
        #pragma unroll
        for (int ni = 0; ni < 8; ni++)
            #pragma unroll
            for (int r = 0; r < 4; r++) acc[mi][ni][r] = 0.0f;

    CP_WAIT0();
    __syncthreads();

    const int delta[9] = {-17, -16, -15, -1, 0, 1, 15, 16, 17};

    for (int j = 0; j < 9; j++) {
        const int tb = 17 + wid * 64 + delta[j] + a_lrow;  // this lane's base row
        const int a_sw = tb & 7;                           // A swizzle phase (const per j)
        const uint32_t wj = wbase + j * WJ_BYTES;
        #pragma unroll
        for (int kk = 0; kk < 4; kk++) {
            const int c0 = kk * 16;
            const uint32_t achunk = (uint32_t)((((c0 + a_lcol) >> 3) ^ a_sw) * 16);
            const uint32_t bchunk = (uint32_t)((((c0 + b_lcol) >> 3) ^ b_sw) * 16);
            uint32_t a[4][4], bb[4][4];
            #pragma unroll
            for (int mi = 0; mi < 4; mi++)
                ldsm4(a[mi][0], a[mi][1], a[mi][2], a[mi][3],
                      xbase + (uint32_t)(tb + mi * 16) * 128 + achunk);
            #pragma unroll
            for (int bi = 0; bi < 4; bi++)
                ldsm4(bb[bi][0], bb[bi][1], bb[bi][2], bb[bi][3],
                      wj + (uint32_t)(bi * 16 + b_lrow) * 128 + bchunk);
            #pragma unroll
            for (int mi = 0; mi < 4; mi++)
                #pragma unroll
                for (int bi = 0; bi < 4; bi++) {
                    mma16816(acc[mi][2 * bi], a[mi], bb[bi] + 0);
                    mma16816(acc[mi][2 * bi + 1], a[mi], bb[bi] + 2);
                }
        }
    }

    // ---- epilogue: D fragment (row=t, col=o), add bias, store ----
    {
        const float* sbias = (const float*)(smem + OFF_BIAS);
        int trow = t0 + wid * 64 + (lane >> 2);
        int ocol = 2 * (lane & 3);
        #pragma unroll
        for (int mi = 0; mi < 4; mi++) {
            #pragma unroll
            for (int ni = 0; ni < 8; ni++) {
                int t = trow + mi * 16;
                int o = ocol + ni * 8;
                size_t base = ((size_t)b * 64 + o) * T_DIM + t;
                float bz0 = sbias[o], bz1 = sbias[o + 1];
                out[base] = acc[mi][ni][0] + bz0;
                out[base + T_DIM] = acc[mi][ni][1] + bz1;
                out[base + 8] = acc[mi][ni][2] + bz0;
                out[base + T_DIM + 8] = acc[mi][ni][3] + bz1;
            }
        }
    }
}

// ============================================================================
// Launch
// ============================================================================
extern "C" void kernel_launch(void* const* d_in, const int* in_sizes, int n_in,
                              void* d_out, int out_size) {
    const float* x = (const float*)d_in[0];
    const float* w = (const float*)d_in[1];
    const float* bias = (const float*)d_in[2];
    float* out = (float*)d_out;

    cudaFuncSetAttribute(ta_main, cudaFuncAttributeMaxDynamicSharedMemorySize, SMEM_TOTAL);

    ta_prep<<<dim3(T_DIM / 64 + 1, B_DIM), 256>>>(x, w);
    ta_main<<<(B_DIM * T_DIM) / TILE_M, 256, SMEM_TOTAL>>>(bias, out);
}